// round 1
// baseline (speedup 1.0000x reference)
#include <cuda_runtime.h>
#include <cstdint>
#include <cstddef>

#define BATCH   32
#define PRIORS  32768
#define NUMC    21
#define NCLS    20
#define NMSK    1000
#define TOPK    200
#define CONF_T  0.01f
#define NMS_T   0.3f
#define NT      256

// Scratch (static device globals; no runtime allocation).
__device__ float  g_conf_t[(size_t)BATCH * NCLS * PRIORS];   // [b][c][p], classes 1..20
__device__ float4 g_decoded[(size_t)BATCH * PRIORS];         // decoded boxes x1,y1,x2,y2

// ---------------------------------------------------------------------------
// Kernel 1: decode boxes + transpose conf so per-class score rows are contiguous
// ---------------------------------------------------------------------------
__global__ void prep_kernel(const float* __restrict__ loc,
                            const float* __restrict__ conf,
                            const float* __restrict__ prior) {
    int idx = blockIdx.x * blockDim.x + threadIdx.x;
    if (idx >= BATCH * PRIORS) return;
    int b = idx >> 15;
    int p = idx & (PRIORS - 1);

    float4 l  = reinterpret_cast<const float4*>(loc)[idx];
    float4 pr = reinterpret_cast<const float4*>(prior)[p];

    // match reference op order: centers = cxy + (loc*0.1)*wh ; wh' = wh*exp(loc*0.2)
    float cx = pr.x + (l.x * 0.1f) * pr.z;
    float cy = pr.y + (l.y * 0.1f) * pr.w;
    float w  = pr.z * expf(l.z * 0.2f);
    float h  = pr.w * expf(l.w * 0.2f);
    float x1 = cx - w * 0.5f;
    float y1 = cy - h * 0.5f;
    g_decoded[idx] = make_float4(x1, y1, x1 + w, y1 + h);

    const float* crow = conf + (size_t)idx * NUMC;
    size_t base = ((size_t)b * NCLS) << 15;
#pragma unroll
    for (int c = 0; c < NCLS; ++c)
        g_conf_t[base + ((size_t)c << 15) + p] = crow[c + 1];
}

// ---------------------------------------------------------------------------
// Kernel 2: per (batch,class) exact top-1000 + greedy NMS + output
// ---------------------------------------------------------------------------
__global__ __launch_bounds__(NT) void nms_kernel(float* __restrict__ out) {
    int bx  = blockIdx.x;           // 0 .. 32*21-1
    int b   = bx / NUMC;
    int cc  = bx % NUMC;
    int tid = threadIdx.x;
    float* outp = out + (size_t)bx * (TOPK * 5);

    if (cc == 0) {                  // background plane: zeros
        for (int i = tid; i < TOPK * 5; i += NT) outp[i] = 0.f;
        return;
    }
    int cls = cc - 1;
    const float4* sc4 = reinterpret_cast<const float4*>(
        g_conf_t + (((size_t)b * NCLS + cls) << 15));

    __shared__ unsigned long long s_keys[2048];                       // 16KB (aliased hist)
    __shared__ float s_x1[1024], s_y1[1024], s_x2[1024], s_y2[1024];
    __shared__ float s_area[1024], s_val[1024];                       // 24KB
    __shared__ unsigned int s_sup[32];
    __shared__ int s_keep[TOPK];
    __shared__ int s_count, s_flag, s_done, s_nkeep, s_kth;
    __shared__ unsigned int s_selbin;
    __shared__ int s_chunk[8];
    int* s_hist = reinterpret_cast<int*>(s_keys);

    // ---- exact radix select: find bits of the 1000th-largest masked score ----
    if (tid == 0) s_kth = NMSK;
    unsigned int prefix = 0, pmask = 0;
#pragma unroll
    for (int pass = 0; pass < 3; ++pass) {
        const int shift = (pass == 0) ? 20 : (pass == 1) ? 8 : 0;
        const int nb    = (pass == 2) ? 256 : 4096;
        __syncthreads();
        for (int i = tid; i < nb; i += NT) s_hist[i] = 0;
        __syncthreads();
        for (int i = tid; i < PRIORS / 4; i += NT) {
            float4 v = sc4[i];
            float vv[4] = {v.x, v.y, v.z, v.w};
#pragma unroll
            for (int c = 0; c < 4; ++c) {
                unsigned int bits = (vv[c] > CONF_T) ? __float_as_uint(vv[c]) : 0u;
                if ((bits & pmask) == prefix)
                    atomicAdd(&s_hist[(bits >> shift) & (nb - 1)], 1);
            }
        }
        __syncthreads();
        if (nb == 4096) {
            int sum = 0;
#pragma unroll
            for (int i = 0; i < 16; ++i) sum += s_hist[tid * 16 + i];
#pragma unroll
            for (int o = 16; o; o >>= 1) sum += __shfl_down_sync(0xffffffffu, sum, o);
            if ((tid & 31) == 0) s_chunk[tid >> 5] = sum;   // 8 chunks of 512 bins
            __syncthreads();
            if (tid == 0) {
                int kth = s_kth, acc = 0, ch;
                for (ch = 7; ch > 0; --ch) {
                    if (acc + s_chunk[ch] >= kth) break;
                    acc += s_chunk[ch];
                }
                int bin = ch * 512 + 511;
                for (;; --bin) {
                    if (acc + s_hist[bin] >= kth) break;
                    acc += s_hist[bin];
                }
                s_kth = kth - acc;
                s_selbin = (unsigned int)bin;
            }
        } else {
            if (tid == 0) {
                int kth = s_kth, acc = 0, bin = 255;
                for (;; --bin) {
                    if (acc + s_hist[bin] >= kth) break;
                    acc += s_hist[bin];
                }
                s_kth = kth - acc;
                s_selbin = (unsigned int)bin;
            }
        }
        __syncthreads();
        prefix |= s_selbin << shift;
        pmask  |= (unsigned int)(nb - 1) << shift;
    }
    const unsigned int pivot = prefix;   // exact bit pattern of 1000th largest

    // ---- gather every element >= pivot as 64-bit key (score desc, index asc) ----
    __syncthreads();                     // hist region dead; reuse as s_keys
    if (tid == 0) s_count = 0;
    __syncthreads();
    for (int i = tid; i < PRIORS / 4; i += NT) {
        float4 v = sc4[i];
        float vv[4] = {v.x, v.y, v.z, v.w};
#pragma unroll
        for (int c = 0; c < 4; ++c) {
            if (vv[c] > CONF_T) {
                unsigned int bits = __float_as_uint(vv[c]);
                if (bits >= pivot) {
                    int pos = atomicAdd(&s_count, 1);
                    if (pos < 2048) {
                        unsigned int p = (unsigned int)(i * 4 + c);
                        s_keys[pos] = ((unsigned long long)bits << 32)
                                    | (unsigned long long)(0xFFFFFFFFu - p);
                    }
                }
            }
        }
    }
    __syncthreads();
    int cnt = s_count < 2048 ? s_count : 2048;
    for (int i = cnt + tid; i < 2048; i += NT) s_keys[i] = 0ull;

    // ---- bitonic sort 2048 keys, descending ----
    for (int k2 = 2; k2 <= 2048; k2 <<= 1) {
        for (int j = k2 >> 1; j > 0; j >>= 1) {
            __syncthreads();
            for (int i = tid; i < 2048; i += NT) {
                int l = i ^ j;
                if (l > i) {
                    unsigned long long a = s_keys[i], bb = s_keys[l];
                    bool up = ((i & k2) == 0);
                    if (up ? (a < bb) : (a > bb)) { s_keys[i] = bb; s_keys[l] = a; }
                }
            }
        }
    }
    __syncthreads();

    // ---- extract top-1000 candidates: score + decoded box + area ----
    const float4* dec = g_decoded + ((size_t)b << 15);
    for (int r = tid; r < 1024; r += NT) {
        float v = 0.f, x1 = 0.f, y1 = 0.f, x2 = 0.f, y2 = 0.f, ar = 0.f;
        if (r < NMSK) {
            unsigned long long key = s_keys[r];
            unsigned int bits = (unsigned int)(key >> 32);
            v = __uint_as_float(bits);
            if (v > CONF_T) {
                unsigned int p = 0xFFFFFFFFu - (unsigned int)(key & 0xFFFFFFFFull);
                float4 bxv = dec[p];
                x1 = bxv.x; y1 = bxv.y; x2 = bxv.z; y2 = bxv.w;
                ar = (x2 - x1) * (y2 - y1);
            }
        }
        s_val[r] = v; s_x1[r] = x1; s_y1[r] = y1;
        s_x2[r] = x2; s_y2[r] = y2; s_area[r] = ar;
    }
    if (tid < 32) s_sup[tid] = 0u;
    if (tid == 0) s_nkeep = 0;
    __syncthreads();

    // ---- greedy NMS, early exit at 200 kept ----
    for (int k = 0; k < NMSK; ++k) {
        if (tid == 0) {
            bool kept = (s_val[k] > CONF_T) && !((s_sup[k >> 5] >> (k & 31)) & 1u);
            s_flag = kept ? 1 : 0;
            if (kept) s_keep[s_nkeep++] = k;
            s_done = (s_nkeep >= TOPK || s_val[k] <= CONF_T) ? 1 : 0;
        }
        __syncthreads();
        if (s_flag) {
            float kx1 = s_x1[k], ky1 = s_y1[k], kx2 = s_x2[k], ky2 = s_y2[k];
            float ka  = s_area[k];
            for (int j = k + 1 + tid; j < NMSK; j += NT) {
                float w = fminf(s_x2[j], kx2) - fmaxf(s_x1[j], kx1);
                float h = fminf(s_y2[j], ky2) - fmaxf(s_y1[j], ky1);
                w = fmaxf(w, 0.f); h = fmaxf(h, 0.f);
                float inter = w * h;
                float iou = inter / (s_area[j] + ka - inter);
                if (iou > NMS_T) atomicOr(&s_sup[j >> 5], 1u << (j & 31));
            }
        }
        if (s_done) break;
        __syncthreads();
    }
    __syncthreads();

    // ---- write 200 rows: [score, x1, y1, x2, y2]; zeros past kept count ----
    int nk = s_nkeep;
    for (int r = tid; r < TOPK; r += NT) {
        float e0 = 0.f, e1 = 0.f, e2 = 0.f, e3 = 0.f, e4 = 0.f;
        if (r < nk) {
            int k = s_keep[r];
            e0 = s_val[k]; e1 = s_x1[k]; e2 = s_y1[k]; e3 = s_x2[k]; e4 = s_y2[k];
        }
        float* row = outp + r * 5;
        row[0] = e0; row[1] = e1; row[2] = e2; row[3] = e3; row[4] = e4;
    }
}

// ---------------------------------------------------------------------------
extern "C" void kernel_launch(void* const* d_in, const int* in_sizes, int n_in,
                              void* d_out, int out_size) {
    const float *loc = nullptr, *conf = nullptr, *prior = nullptr;
    for (int i = 0; i < n_in; ++i) {
        long long sz = in_sizes[i];
        if      (sz == (long long)BATCH * PRIORS * 4)    loc   = (const float*)d_in[i];
        else if (sz == (long long)BATCH * PRIORS * NUMC) conf  = (const float*)d_in[i];
        else if (sz == (long long)PRIORS * 4)            prior = (const float*)d_in[i];
    }
    prep_kernel<<<(BATCH * PRIORS + 255) / 256, 256>>>(loc, conf, prior);
    nms_kernel<<<BATCH * NUMC, NT>>>((float*)d_out);
    (void)out_size;
}

// round 2
// speedup vs baseline: 1.1830x; 1.1830x over previous
#include <cuda_runtime.h>
#include <cstdint>
#include <cstddef>

#define BATCH   32
#define PRIORS  32768
#define NUMC    21
#define NCLS    20
#define NMSK    1000
#define TOPK    200
#define CONF_T  0.01f
#define NMS_T   0.3f
#define NT      256

#define HBINS   8192          // top-13 bits of float
#define HSHIFT  19
#define BUFCAP  2944          // gathered-candidate cap

// s_scal slots
#define I_CNT    0
#define I_SELCH  1
#define I_KTHA   2
#define I_SELBIN 3
#define I_SELBY  4
#define I_KTH2   5
#define I_CNT2   6

__device__ float  g_conf_t[(size_t)BATCH * NCLS * PRIORS];   // [b][c][p]
__device__ float4 g_decoded[(size_t)BATCH * PRIORS];

// ---------------------------------------------------------------------------
// Kernel 1: decode boxes + transpose conf
// ---------------------------------------------------------------------------
__global__ void prep_kernel(const float* __restrict__ loc,
                            const float* __restrict__ conf,
                            const float* __restrict__ prior) {
    int idx = blockIdx.x * blockDim.x + threadIdx.x;
    if (idx >= BATCH * PRIORS) return;
    int b = idx >> 15;
    int p = idx & (PRIORS - 1);

    float4 l  = reinterpret_cast<const float4*>(loc)[idx];
    float4 pr = reinterpret_cast<const float4*>(prior)[p];

    float cx = pr.x + (l.x * 0.1f) * pr.z;
    float cy = pr.y + (l.y * 0.1f) * pr.w;
    float w  = pr.z * expf(l.z * 0.2f);
    float h  = pr.w * expf(l.w * 0.2f);
    float x1 = cx - w * 0.5f;
    float y1 = cy - h * 0.5f;
    g_decoded[idx] = make_float4(x1, y1, x1 + w, y1 + h);

    const float* crow = conf + (size_t)idx * NUMC;
    size_t base = ((size_t)b * NCLS) << 15;
#pragma unroll
    for (int c = 0; c < NCLS; ++c)
        g_conf_t[base + ((size_t)c << 15) + p] = crow[c + 1];
}

// ---------------------------------------------------------------------------
// Kernel 2: per (batch,class) exact top-1000 + greedy NMS + output
// ---------------------------------------------------------------------------
__global__ __launch_bounds__(NT) void nms_kernel(float* __restrict__ out) {
    int bx  = blockIdx.x;
    int b   = bx / NUMC;
    int cc  = bx % NUMC;
    int tid = threadIdx.x;
    float* outp = out + (size_t)bx * (TOPK * 5);

    if (cc == 0) {
        for (int i = tid; i < TOPK * 5; i += NT) outp[i] = 0.f;
        return;
    }
    int cls = cc - 1;
    const float4* sc4 = reinterpret_cast<const float4*>(
        g_conf_t + (((size_t)b * NCLS + cls) << 15));

    // 32KB overlaid arena + small scratch
    __shared__ __align__(16) unsigned char s_mem[32768];
    __shared__ int s_aux[256];
    __shared__ unsigned int s_sup[32];
    __shared__ int s_keep[TOPK];
    __shared__ int s_scal[8];

    unsigned long long* s_dst = reinterpret_cast<unsigned long long*>(s_mem);          // [0,8KB)  1024 keys
    unsigned long long* s_buf = reinterpret_cast<unsigned long long*>(s_mem + 8192);   // [8,31KB) 2944 keys
    int*   s_hist = reinterpret_cast<int*>(s_mem);                                     // [0,32KB) aliases both
    float* s_x1   = reinterpret_cast<float*>(s_mem + 8192);                            // boxes alias s_buf
    float* s_y1   = s_x1 + 1024;
    float* s_x2   = s_y1 + 1024;
    float* s_y2   = s_x2 + 1024;
    float* s_val  = s_y2 + 1024;
    float* s_area = s_val + 1024;

    const unsigned int FULL = 0xffffffffu;
    const int lane = tid & 31;

    // ---- Phase 1: 13-bit histogram (one scan) ----
    for (int i = tid; i < HBINS; i += NT) s_hist[i] = 0;
    __syncthreads();
    for (int i = tid; i < PRIORS / 4; i += NT) {
        float4 v = sc4[i];
        float vv[4] = {v.x, v.y, v.z, v.w};
#pragma unroll
        for (int c = 0; c < 4; ++c) {
            unsigned int bits = (vv[c] > CONF_T) ? __float_as_uint(vv[c]) : 0u;
            atomicAdd(&s_hist[bits >> HSHIFT], 1);
        }
    }
    __syncthreads();

    // ---- Phase 2: parallel suffix over 256 chunk-sums -> pivot bin ----
    {
        int s = 0;
        int base = tid * 32;
#pragma unroll
        for (int j = 0; j < 32; ++j) s += s_hist[base + ((j + tid) & 31)];
        s_aux[tid] = s;
    }
    __syncthreads();
    for (int d = 1; d < 256; d <<= 1) {
        int v = 0;
        int idx = tid + d;
        if (idx < 256) v = s_aux[idx];
        __syncthreads();
        s_aux[tid] += v;
        __syncthreads();
    }
    {
        int suf  = s_aux[tid];
        int sufn = (tid < 255) ? s_aux[tid + 1] : 0;
        if (suf >= NMSK && sufn < NMSK) {
            s_scal[I_SELCH] = tid;
            s_scal[I_KTHA]  = NMSK - sufn;
        }
    }
    __syncthreads();
    if (tid < 32) {
        int selc = s_scal[I_SELCH];
        int kthA = s_scal[I_KTHA];
        int h    = s_hist[selc * 32 + tid];
        int suf  = h;
#pragma unroll
        for (int o = 1; o < 32; o <<= 1) {
            int t = __shfl_down_sync(FULL, suf, o);
            if (tid + o < 32) suf += t;
        }
        int sufn = __shfl_down_sync(FULL, suf, 1);
        if (tid == 31) sufn = 0;
        if (suf >= kthA && sufn < kthA) s_scal[I_SELBIN] = selc * 32 + tid;
    }
    __syncthreads();
    const unsigned int pivot = ((unsigned int)s_scal[I_SELBIN]) << HSHIFT;

    // ---- Phase 3: gather candidates >= pivot (scan 2); zero dst ----
    if (tid == 0) { s_scal[I_CNT] = 0; s_scal[I_CNT2] = 0; }
    for (int i = tid; i < 1024; i += NT) s_dst[i] = 0ull;
    __syncthreads();
    for (int i = tid; i < PRIORS / 4; i += NT) {
        float4 v = sc4[i];
        float vv[4] = {v.x, v.y, v.z, v.w};
#pragma unroll
        for (int c = 0; c < 4; ++c) {
            if (vv[c] > CONF_T) {
                unsigned int bits = __float_as_uint(vv[c]);
                if (bits >= pivot) {
                    int pos = atomicAdd(&s_scal[I_CNT], 1);
                    if (pos < BUFCAP) {
                        unsigned int p = (unsigned int)(i * 4 + c);
                        s_buf[pos] = ((unsigned long long)bits << 32)
                                   | (unsigned long long)(0xFFFFFFFFu - p);
                    }
                }
            }
        }
    }
    __syncthreads();
    int cnt = s_scal[I_CNT];
    if (cnt > BUFCAP) cnt = BUFCAP;

    // ---- Phase 4: in-smem exact 64-bit radix select of rank-1000 key ----
    unsigned long long kth64 = 0;
    if (cnt > NMSK) {
        unsigned long long pref = 0, msk = 0;
        int kth = NMSK;
#pragma unroll 1
        for (int pass = 0; pass < 8; ++pass) {
            int shift = 56 - pass * 8;
            s_aux[tid] = 0;
            __syncthreads();
            for (int i = tid; i < cnt; i += NT) {
                unsigned long long k = s_buf[i];
                if ((k & msk) == pref)
                    atomicAdd(&s_aux[(int)((k >> shift) & 0xFF)], 1);
            }
            __syncthreads();
            if (tid < 32) {
                int base = tid * 8;
                int h[8]; int s = 0;
#pragma unroll
                for (int j = 0; j < 8; ++j) { h[j] = s_aux[base + j]; s += h[j]; }
                int suf = s;
#pragma unroll
                for (int o = 1; o < 32; o <<= 1) {
                    int t = __shfl_down_sync(FULL, suf, o);
                    if (tid + o < 32) suf += t;
                }
                int sufn = __shfl_down_sync(FULL, suf, 1);
                if (tid == 31) sufn = 0;
                if (suf >= kth && sufn < kth) {
                    int kk = kth - sufn;       // rank within this lane's 8 bins
                    int run = 0;
#pragma unroll
                    for (int j = 7; j >= 0; --j) {
                        run += h[j];
                        if (run >= kk) {
                            s_scal[I_SELBY] = base + j;
                            s_scal[I_KTH2]  = kk - (run - h[j]);
                            break;
                        }
                    }
                }
            }
            __syncthreads();
            pref |= ((unsigned long long)(unsigned int)s_scal[I_SELBY]) << shift;
            msk  |= 0xFFull << shift;
            kth   = s_scal[I_KTH2];
        }
        kth64 = pref;
    }

    // ---- Phase 5: partition exactly top-1000 into s_dst ----
    __syncthreads();
    if (cnt > NMSK) {
        for (int i = tid; i < cnt; i += NT) {
            unsigned long long k = s_buf[i];
            if (k > kth64) {
                int p = atomicAdd(&s_scal[I_CNT2], 1);
                if (p < 1024) s_dst[p] = k;
            } else if (k == kth64) {
                s_dst[NMSK - 1] = k;
            }
        }
    } else {
        for (int i = tid; i < cnt; i += NT) s_dst[i] = s_buf[i];
    }

    // ---- Phase 6: bitonic sort 1024 keys, descending ----
    for (int k2 = 2; k2 <= 1024; k2 <<= 1) {
        for (int j = k2 >> 1; j > 0; j >>= 1) {
            __syncthreads();
            for (int i = tid; i < 1024; i += NT) {
                int l = i ^ j;
                if (l > i) {
                    unsigned long long a = s_dst[i], bb = s_dst[l];
                    bool up = ((i & k2) == 0);
                    if (up ? (a < bb) : (a > bb)) { s_dst[i] = bb; s_dst[l] = a; }
                }
            }
        }
    }
    __syncthreads();

    // ---- Phase 7: extract boxes (s_buf dead; boxes alias it) ----
    const float4* dec = g_decoded + ((size_t)b << 15);
    for (int r = tid; r < 1024; r += NT) {
        float v = 0.f, x1 = 0.f, y1 = 0.f, x2 = 0.f, y2 = 0.f, ar = 0.f;
        if (r < NMSK) {
            unsigned long long key = s_dst[r];
            unsigned int bits = (unsigned int)(key >> 32);
            v = __uint_as_float(bits);
            if (v > CONF_T) {
                unsigned int p = 0xFFFFFFFFu - (unsigned int)(key & 0xFFFFFFFFull);
                float4 bxv = dec[p];
                x1 = bxv.x; y1 = bxv.y; x2 = bxv.z; y2 = bxv.w;
                ar = (x2 - x1) * (y2 - y1);
            }
        }
        s_val[r] = v; s_x1[r] = x1; s_y1[r] = y1;
        s_x2[r] = x2; s_y2[r] = y2; s_area[r] = ar;
    }
    if (tid < 32) s_sup[tid] = 0u;
    __syncthreads();

    // ---- Phase 8: greedy NMS, ONE barrier per kept candidate ----
    int nkeep = 0;
    for (int k = 0; k < NMSK; ++k) {
        float vk = s_val[k];
        if (vk <= CONF_T) break;                        // uniform across block
        bool sup = (s_sup[k >> 5] >> (k & 31)) & 1u;    // consistent post-barrier
        if (!sup) {
            if (tid == 0) s_keep[nkeep] = k;
            nkeep++;
            if (nkeep >= TOPK) break;
            float kx1 = s_x1[k], ky1 = s_y1[k], kx2 = s_x2[k], ky2 = s_y2[k];
            float ka  = s_area[k];
            for (int j = k + 1 + tid; j < NMSK; j += NT) {
                float w = fminf(s_x2[j], kx2) - fmaxf(s_x1[j], kx1);
                float h = fminf(s_y2[j], ky2) - fmaxf(s_y1[j], ky1);
                w = fmaxf(w, 0.f); h = fmaxf(h, 0.f);
                float inter = w * h;
                float iou = inter / (s_area[j] + ka - inter);
                if (iou > NMS_T) atomicOr(&s_sup[j >> 5], 1u << (j & 31));
            }
            __syncthreads();
        }
    }
    __syncthreads();

    // ---- Phase 9: write output ----
    for (int r = tid; r < TOPK; r += NT) {
        float e0 = 0.f, e1 = 0.f, e2 = 0.f, e3 = 0.f, e4 = 0.f;
        if (r < nkeep) {
            int k = s_keep[r];
            e0 = s_val[k]; e1 = s_x1[k]; e2 = s_y1[k]; e3 = s_x2[k]; e4 = s_y2[k];
        }
        float* row = outp + r * 5;
        row[0] = e0; row[1] = e1; row[2] = e2; row[3] = e3; row[4] = e4;
    }
}

// ---------------------------------------------------------------------------
extern "C" void kernel_launch(void* const* d_in, const int* in_sizes, int n_in,
                              void* d_out, int out_size) {
    const float *loc = nullptr, *conf = nullptr, *prior = nullptr;
    for (int i = 0; i < n_in; ++i) {
        long long sz = in_sizes[i];
        if      (sz == (long long)BATCH * PRIORS * 4)    loc   = (const float*)d_in[i];
        else if (sz == (long long)BATCH * PRIORS * NUMC) conf  = (const float*)d_in[i];
        else if (sz == (long long)PRIORS * 4)            prior = (const float*)d_in[i];
    }
    prep_kernel<<<(BATCH * PRIORS + 255) / 256, 256>>>(loc, conf, prior);
    nms_kernel<<<BATCH * NUMC, NT>>>((float*)d_out);
    (void)out_size;
}